// round 1
// baseline (speedup 1.0000x reference)
#include <cuda_runtime.h>
#include <math.h>

#define L_  4
#define B_  8
#define H_  16
#define S_  4096
#define HD_ 64
#define D_  1024
#define Q_  4
#define V_  32000
#define SP_ (S_ + Q_)      // 4100
#define M32 (B_ * Q_)      // 32
#define SCALE_ 0.125f      // 1/sqrt(64)

// ------------------------- scratch (no allocs allowed) ----------------------
__device__ float g_x[M32 * D_];
__device__ float g_qkv[M32 * 3 * D_];
__device__ float g_o[M32 * D_];
__device__ float g_h[M32 * 4 * D_];

// ------------------------------ embedding -----------------------------------
__global__ void embed_kernel(const int* __restrict__ ids, const int* __restrict__ pos,
                             const float* __restrict__ emb, const float* __restrict__ pemb) {
    int m = blockIdx.x;                       // 0..31  (b*Q+q)
    int id = ids[m];
    int p  = pos[m];
    const float* e  = emb  + (size_t)id * D_;
    const float* pe = pemb + (size_t)p  * D_;
    for (int d = threadIdx.x; d < D_; d += blockDim.x)
        g_x[m * D_ + d] = e[d] + pe[d];
}

// ------------------------------ skinny GEMM ---------------------------------
// C[m,n] = dot(A[m,:], W[n,:])  with M=32 fixed.
// mode 0: store, mode 1: C = res + A@W^T, mode 2: relu(A@W^T)
// Block: 256 threads = 8 warps; warp g owns NT consecutive n; lane = m.
template <int NT>
__global__ void gemm32_kernel(const float* __restrict__ A, const float* __restrict__ W,
                              const float* __restrict__ res, float* __restrict__ C,
                              int N, int K, int mode) {
    const int BK = 128;
    __shared__ float a_sm[BK][33];            // transposed + padded: LDS conflict-free
    int t = threadIdx.x;
    int m = t & 31;
    int g = t >> 5;                           // warp id 0..7
    int n0 = blockIdx.x * (8 * NT) + g * NT;

    float acc[NT];
#pragma unroll
    for (int j = 0; j < NT; j++) acc[j] = 0.f;

    for (int kc = 0; kc < K; kc += BK) {
        // cooperative load of A chunk [32][BK], stored transposed
#pragma unroll
        for (int i = 0; i < (32 * BK) / 256; i++) {
            int idx = t + i * 256;
            int mm = idx >> 7;                // idx / BK (BK==128)
            int kk = idx & 127;
            a_sm[kk][mm] = A[(size_t)mm * K + kc + kk];
        }
        __syncthreads();

        const float* w0 = W + (size_t)n0 * K + kc;
#pragma unroll 4
        for (int k4 = 0; k4 < BK; k4 += 4) {
            float4 wv[NT];
#pragma unroll
            for (int j = 0; j < NT; j++)
                wv[j] = *reinterpret_cast<const float4*>(w0 + (size_t)j * K + k4);
#pragma unroll
            for (int kk = 0; kk < 4; kk++) {
                float av = a_sm[k4 + kk][m];
#pragma unroll
                for (int j = 0; j < NT; j++)
                    acc[j] += av * (&wv[j].x)[kk];
            }
        }
        __syncthreads();
    }

#pragma unroll
    for (int j = 0; j < NT; j++) {
        int n = n0 + j;
        float vo = acc[j];
        if (mode == 1)      vo += res[(size_t)m * N + n];
        else if (mode == 2) vo = fmaxf(vo, 0.f);
        C[(size_t)m * N + n] = vo;
    }
}

// --------------------------- fused attention + KV copy ----------------------
// One block per (b,h). Full (non-causal) softmax over S+Q keys, per reference.
// Pass 1 streams past K, computes 4 q-dots per row, and writes the row to
// pres_k (the copy is free on top of the read). Pass 2 streams past V,
// accumulates P·V, and writes pres_v.
__global__ void attn_kernel(const float* __restrict__ qkv,
                            const float* __restrict__ pk, const float* __restrict__ pv,
                            float* __restrict__ ok, float* __restrict__ ov,
                            float* __restrict__ o) {
    extern __shared__ float sm[];
    float* q_sm  = sm;                 // [4][64], pre-scaled
    float* kn    = sm + 256;           // new K rows [4][64]
    float* vn    = sm + 512;           // new V rows [4][64]
    float* red   = sm + 768;           // [256] reduction scratch
    float* inv4  = sm + 1024;          // [4] (padded to 32)
    float* opart = sm + 1056;          // [4 sg][4 qq][64 d]
    float* sc    = sm + 2080;          // [4][SP_] scores

    int t = threadIdx.x;
    int b = blockIdx.x >> 4;
    int h = blockIdx.x & 15;

    {   // load q (pre-scaled), new k, new v  — exactly 256 elements each
        int qq = t >> 6, d = t & 63;
        int row = (b * Q_ + qq) * 3 * D_ + h * HD_ + d;
        q_sm[t] = qkv[row] * SCALE_;
        kn[t]   = qkv[row + D_];
        vn[t]   = qkv[row + 2 * D_];
    }
    __syncthreads();

    size_t bh = (size_t)(b * H_ + h);
    const float* kb  = pk + bh * S_ * HD_;
    float*       okb = ok + bh * SP_ * HD_;

    // ---- pass 1: scores + K copy-out ----
    for (int s = t; s < SP_; s += 256) {
        const float* kr = (s < S_) ? (kb + (size_t)s * HD_) : (kn + (s - S_) * HD_);
        float4* dst = reinterpret_cast<float4*>(okb + (size_t)s * HD_);
        float d0 = 0.f, d1 = 0.f, d2 = 0.f, d3 = 0.f;
#pragma unroll
        for (int j = 0; j < 16; j++) {
            float4 kv = reinterpret_cast<const float4*>(kr)[j];
            dst[j] = kv;
            int c = j * 4;
            d0 += kv.x * q_sm[c]       + kv.y * q_sm[c + 1]       + kv.z * q_sm[c + 2]       + kv.w * q_sm[c + 3];
            d1 += kv.x * q_sm[64 + c]  + kv.y * q_sm[64 + c + 1]  + kv.z * q_sm[64 + c + 2]  + kv.w * q_sm[64 + c + 3];
            d2 += kv.x * q_sm[128 + c] + kv.y * q_sm[128 + c + 1] + kv.z * q_sm[128 + c + 2] + kv.w * q_sm[128 + c + 3];
            d3 += kv.x * q_sm[192 + c] + kv.y * q_sm[192 + c + 1] + kv.z * q_sm[192 + c + 2] + kv.w * q_sm[192 + c + 3];
        }
        sc[0 * SP_ + s] = d0;
        sc[1 * SP_ + s] = d1;
        sc[2 * SP_ + s] = d2;
        sc[3 * SP_ + s] = d3;
    }
    __syncthreads();

    // ---- softmax (per query) ----
    for (int qq = 0; qq < 4; qq++) {
        float* scq = sc + qq * SP_;
        float mx = -1e30f;
        for (int s = t; s < SP_; s += 256) mx = fmaxf(mx, scq[s]);
        red[t] = mx;
        __syncthreads();
        for (int w = 128; w > 0; w >>= 1) {
            if (t < w) red[t] = fmaxf(red[t], red[t + w]);
            __syncthreads();
        }
        mx = red[0];
        __syncthreads();
        float sum = 0.f;
        for (int s = t; s < SP_; s += 256) {
            float e = __expf(scq[s] - mx);
            scq[s] = e;
            sum += e;
        }
        red[t] = sum;
        __syncthreads();
        for (int w = 128; w > 0; w >>= 1) {
            if (t < w) red[t] += red[t + w];
            __syncthreads();
        }
        if (t == 0) inv4[qq] = 1.f / red[0];
        __syncthreads();
    }

    // ---- pass 2: O = P·V + V copy-out ----
    // thread → (sg: s-range, qq, dg: 4-float d slice). 4 sgroups partial-sum.
    const float* vb  = pv + bh * S_ * HD_;
    float*       ovb = ov + bh * SP_ * HD_;
    int dg = (t & 15) * 4;
    int qq = (t >> 4) & 3;
    int sg = t >> 6;
    const float* scq = sc + qq * SP_;

    float4 acc = make_float4(0.f, 0.f, 0.f, 0.f);
    int s0 = sg * (S_ / 4);
    for (int s = s0; s < s0 + S_ / 4; s += 8) {
        float4 vv[8];
#pragma unroll
        for (int u = 0; u < 8; u++)
            vv[u] = *reinterpret_cast<const float4*>(vb + (size_t)(s + u) * HD_ + dg);
#pragma unroll
        for (int u = 0; u < 8; u++) {
            float p = scq[s + u];
            acc.x += p * vv[u].x; acc.y += p * vv[u].y;
            acc.z += p * vv[u].z; acc.w += p * vv[u].w;
            if (qq == 0)
                *reinterpret_cast<float4*>(ovb + (size_t)(s + u) * HD_ + dg) = vv[u];
        }
    }
    if (sg == 0) {   // new V rows: each (qq,dg) contributes once
#pragma unroll
        for (int u = 0; u < 4; u++) {
            int s = S_ + u;
            float4 vv = *reinterpret_cast<const float4*>(vn + u * HD_ + dg);
            float p = scq[s];
            acc.x += p * vv.x; acc.y += p * vv.y;
            acc.z += p * vv.z; acc.w += p * vv.w;
            if (qq == 0)
                *reinterpret_cast<float4*>(ovb + (size_t)s * HD_ + dg) = vv;
        }
    }
    *reinterpret_cast<float4*>(&opart[sg * 256 + qq * 64 + dg]) = acc;
    __syncthreads();

    {   // cross-sgroup reduce + normalize + write o
        int qq2 = t >> 6, d = t & 63;
        float r = opart[0 * 256 + qq2 * 64 + d] + opart[1 * 256 + qq2 * 64 + d]
                + opart[2 * 256 + qq2 * 64 + d] + opart[3 * 256 + qq2 * 64 + d];
        o[(b * Q_ + qq2) * D_ + h * HD_ + d] = r * inv4[qq2];
    }
}

// ------------------------------- launcher -----------------------------------
extern "C" void kernel_launch(void* const* d_in, const int* in_sizes, int n_in,
                              void* d_out, int out_size) {
    const int*   ids    = (const int*)d_in[0];
    const int*   pos    = (const int*)d_in[1];
    const float* past_k = (const float*)d_in[2];
    const float* past_v = (const float*)d_in[3];
    const float* emb    = (const float*)d_in[4];
    const float* pemb   = (const float*)d_in[5];
    const float* qkv_w  = (const float*)d_in[6];
    const float* out_w  = (const float*)d_in[7];
    const float* fc1_w  = (const float*)d_in[8];
    const float* fc2_w  = (const float*)d_in[9];
    const float* lm_w   = (const float*)d_in[10];

    float* out    = (float*)d_out;
    float* logits = out;                                         // [32, 32000]
    float* pres_k = out + (size_t)M32 * V_;                      // [L,B,H,SP,HD]
    float* pres_v = pres_k + (size_t)L_ * B_ * H_ * SP_ * HD_;

    float *x, *qkvb, *ob, *hb;
    cudaGetSymbolAddress((void**)&x,    g_x);
    cudaGetSymbolAddress((void**)&qkvb, g_qkv);
    cudaGetSymbolAddress((void**)&ob,   g_o);
    cudaGetSymbolAddress((void**)&hb,   g_h);

    const int ATTN_SMEM = (2080 + 4 * SP_) * 4;   // 73920 bytes
    cudaFuncSetAttribute(attn_kernel, cudaFuncAttributeMaxDynamicSharedMemorySize, ATTN_SMEM);

    embed_kernel<<<M32, 256>>>(ids, pos, emb, pemb);

    for (int l = 0; l < L_; l++) {
        // qkv = x @ qkv_w^T                       N=3072, K=1024
        gemm32_kernel<4><<<(3 * D_) / 32, 256>>>(x, qkv_w + (size_t)l * 3 * D_ * D_,
                                                 nullptr, qkvb, 3 * D_, D_, 0);
        // attention + KV cache copy
        attn_kernel<<<B_ * H_, 256, ATTN_SMEM>>>(
            qkvb,
            past_k + (size_t)l * B_ * H_ * S_ * HD_,
            past_v + (size_t)l * B_ * H_ * S_ * HD_,
            pres_k + (size_t)l * B_ * H_ * SP_ * HD_,
            pres_v + (size_t)l * B_ * H_ * SP_ * HD_,
            ob);
        // x = x + o @ out_w^T                     N=1024, K=1024
        gemm32_kernel<1><<<D_ / 8, 256>>>(ob, out_w + (size_t)l * D_ * D_,
                                          x, x, D_, D_, 1);
        // h = relu(x @ fc1_w^T)                   N=4096, K=1024
        gemm32_kernel<4><<<(4 * D_) / 32, 256>>>(x, fc1_w + (size_t)l * 4 * D_ * D_,
                                                 nullptr, hb, 4 * D_, D_, 2);
        // x = x + h @ fc2_w^T                     N=1024, K=4096
        gemm32_kernel<1><<<D_ / 8, 256>>>(hb, fc2_w + (size_t)l * D_ * 4 * D_,
                                          x, x, D_, 4 * D_, 1);
    }

    // logits = x @ lm_head^T                      N=32000, K=1024
    gemm32_kernel<4><<<V_ / 32, 256>>>(x, lm_w, nullptr, logits, V_, D_, 0);
}

// round 2
// speedup vs baseline: 3.3701x; 3.3701x over previous
#include <cuda_runtime.h>
#include <math.h>

#define L_  4
#define B_  8
#define H_  16
#define S_  4096
#define HD_ 64
#define D_  1024
#define Q_  4
#define V_  32000
#define SP_ (S_ + Q_)      // 4100
#define M32 (B_ * Q_)      // 32
#define SCALE_ 0.125f      // 1/sqrt(64)
#define BK_ 256

// ------------------------- scratch (no allocs allowed) ----------------------
__device__ float g_x[M32 * D_];
__device__ float g_qkv[M32 * 3 * D_];
__device__ float g_o[M32 * D_];
__device__ float g_h[M32 * 4 * D_];
__device__ float g_part[4 * M32 * 4096];   // split-K partials (KS<=4, N<=4096)

// ------------------------------ embedding -----------------------------------
__global__ void embed_kernel(const int* __restrict__ ids, const int* __restrict__ pos,
                             const float* __restrict__ emb, const float* __restrict__ pemb) {
    int m = blockIdx.x;
    int id = ids[m];
    int p  = pos[m];
    const float* e  = emb  + (size_t)id * D_;
    const float* pe = pemb + (size_t)p  * D_;
    for (int d = threadIdx.x; d < D_; d += blockDim.x)
        g_x[m * D_ + d] = e[d] + pe[d];
}

// ------------------------------ skinny GEMM ---------------------------------
// C[m,n] = dot(A[m,:], W[n,:]), M=32. BN=32 n per block, 8 warps x NT=4 n.
// Both W and A tiles are staged through smem with fully-coalesced global loads
// and register-prefetch double buffering. Compute: lane=m, a via swizzled
// float4 LDS (conflict-free), w via broadcast float4 LDS.
// kslen==K: write C with mode (0 store, 1 +res, 2 relu).
// kslen<K : grid.x = (N/32)*KS, write partials to Cout = g_part.
__global__ void __launch_bounds__(256, 2)
gemm32_kernel(const float* __restrict__ A, const float* __restrict__ W,
              const float* __restrict__ res, float* __restrict__ Cout,
              int N, int K, int kslen, int mode) {
    extern __shared__ float sm[];
    float4* w_sm4 = reinterpret_cast<float4*>(sm);            // [32][64] float4
    float4* a_sm4 = reinterpret_cast<float4*>(sm + 32 * BK_); // [64][32] float4 swizzled

    int t = threadIdx.x;
    int m = t & 31;
    int g = t >> 5;
    int nblocks = N >> 5;
    int nb = blockIdx.x % nblocks;
    int ks = blockIdx.x / nblocks;
    int k0 = ks * kslen;

    // loader mapping: 2048 float4 per tile, 8 per thread
    int lrow = t >> 6;          // 0..3, + 4*j
    int lcol = t & 63;          // float4 column within chunk

    const float* Wg = W + (size_t)(nb * 32 + lrow) * K + k0 + (size_t)lcol * 4;
    const float* Ag = A + (size_t)lrow * K + k0 + (size_t)lcol * 4;

    float4 wreg[8], areg[8];
#pragma unroll
    for (int j = 0; j < 8; j++) {
        wreg[j] = *reinterpret_cast<const float4*>(Wg + (size_t)(4 * j) * K);
        areg[j] = *reinterpret_cast<const float4*>(Ag + (size_t)(4 * j) * K);
    }

    float acc[4] = {0.f, 0.f, 0.f, 0.f};

    for (int kc = 0; kc < kslen; kc += BK_) {
        // commit prefetched tile to smem
#pragma unroll
        for (int j = 0; j < 8; j++) {
            int row = lrow + 4 * j;
            w_sm4[row * 64 + lcol] = wreg[j];
            a_sm4[lcol * 32 + (row ^ (lcol & 31))] = areg[j];
        }
        __syncthreads();

        if (kc + BK_ < kslen) {
#pragma unroll
            for (int j = 0; j < 8; j++) {
                wreg[j] = *reinterpret_cast<const float4*>(Wg + (size_t)(4 * j) * K + kc + BK_);
                areg[j] = *reinterpret_cast<const float4*>(Ag + (size_t)(4 * j) * K + kc + BK_);
            }
        }

        const float4* wrow = w_sm4 + g * 4 * 64;
#pragma unroll 4
        for (int kk4 = 0; kk4 < 64; kk4++) {
            float4 av = a_sm4[kk4 * 32 + (m ^ (kk4 & 31))];
            float4 w0 = wrow[kk4];
            float4 w1 = wrow[64 + kk4];
            float4 w2 = wrow[128 + kk4];
            float4 w3 = wrow[192 + kk4];
            acc[0] += av.x * w0.x + av.y * w0.y + av.z * w0.z + av.w * w0.w;
            acc[1] += av.x * w1.x + av.y * w1.y + av.z * w1.z + av.w * w1.w;
            acc[2] += av.x * w2.x + av.y * w2.y + av.z * w2.z + av.w * w2.w;
            acc[3] += av.x * w3.x + av.y * w3.y + av.z * w3.z + av.w * w3.w;
        }
        __syncthreads();
    }

    int n0 = nb * 32 + g * 4;
    if (kslen == K) {
#pragma unroll
        for (int j = 0; j < 4; j++) {
            int n = n0 + j;
            float v = acc[j];
            if (mode == 1)      v += res[(size_t)m * N + n];
            else if (mode == 2) v = fmaxf(v, 0.f);
            Cout[(size_t)m * N + n] = v;
        }
    } else {
#pragma unroll
        for (int j = 0; j < 4; j++)
            Cout[(size_t)(ks * 32 + m) * N + n0 + j] = acc[j];
    }
}

// split-K reduce: C = mode(sum_ks P, res)
__global__ void reduce_kernel(const float* __restrict__ P, const float* __restrict__ res,
                              float* __restrict__ C, int N, int KS, int mode) {
    int i = blockIdx.x * 256 + threadIdx.x;
    if (i >= 32 * N) return;
    float s = 0.f;
    for (int ks = 0; ks < KS; ks++) s += P[(size_t)ks * 32 * N + i];
    if (mode == 1)      s += res[i];
    else if (mode == 2) s = fmaxf(s, 0.f);
    C[i] = s;
}

// --------------------------- fused attention + KV copy ----------------------
// One block (512 thr) per (b,h). All global K/V traffic is coalesced:
// warp handles 2 rows per step; lane = (row-half sub, d-quarter dq).
// Pass 1: stream K -> scores (shfl-reduce over 16 lanes) + pres_k copy.
// Pass 2: stream V once, accumulate all 4 queries per lane + pres_v copy.
__global__ void __launch_bounds__(512, 1)
attn_kernel(const float* __restrict__ qkv,
            const float* __restrict__ pk, const float* __restrict__ pv,
            float* __restrict__ ok, float* __restrict__ ov,
            float* __restrict__ o) {
    extern __shared__ float sm[];
    float* q_sm  = sm;            // [4][64] pre-scaled
    float* kn    = sm + 256;      // new K rows [4][64]
    float* vn    = sm + 512;      // new V rows [4][64]
    float* red   = sm + 768;      // [512]
    float* inv4  = sm + 1280;     // [4] (padded)
    float* opart = sm + 1312;     // [16 warps][4 qq][64 d]
    float* scT   = sm + 5408;     // [SP][4] interleaved scores

    int t = threadIdx.x;
    int b = blockIdx.x >> 4;
    int h = blockIdx.x & 15;

    if (t < 256) {
        int qq = t >> 6, d = t & 63;
        int rowi = (b * Q_ + qq) * 3 * D_ + h * HD_ + d;
        q_sm[t] = qkv[rowi] * SCALE_;
        kn[t]   = qkv[rowi + D_];
        vn[t]   = qkv[rowi + 2 * D_];
    }
    __syncthreads();

    int w   = t >> 5;
    int l   = t & 31;
    int sub = l >> 4;         // 0/1: which of the 2 rows
    int dq  = l & 15;         // d-quarter (4 floats)

    size_t bh = (size_t)(b * H_ + h);
    const float* kb  = pk + bh * S_ * HD_;
    float*       okb = ok + bh * SP_ * HD_;

    float4 q0 = *reinterpret_cast<const float4*>(q_sm +       dq * 4);
    float4 q1 = *reinterpret_cast<const float4*>(q_sm +  64 + dq * 4);
    float4 q2 = *reinterpret_cast<const float4*>(q_sm + 128 + dq * 4);
    float4 q3 = *reinterpret_cast<const float4*>(q_sm + 192 + dq * 4);

    // ---- pass 1: K stream -> scores + pres_k ----
    for (int base = w * 4; base < 2048; base += 64) {
        float4 kv[4];
#pragma unroll
        for (int u = 0; u < 4; u++) {
            int row = (base + u) * 2 + sub;
            kv[u] = *reinterpret_cast<const float4*>(kb + (size_t)row * HD_ + dq * 4);
        }
#pragma unroll
        for (int u = 0; u < 4; u++) {
            int row = (base + u) * 2 + sub;
            *reinterpret_cast<float4*>(okb + (size_t)row * HD_ + dq * 4) = kv[u];
            float p0 = kv[u].x * q0.x + kv[u].y * q0.y + kv[u].z * q0.z + kv[u].w * q0.w;
            float p1 = kv[u].x * q1.x + kv[u].y * q1.y + kv[u].z * q1.z + kv[u].w * q1.w;
            float p2 = kv[u].x * q2.x + kv[u].y * q2.y + kv[u].z * q2.z + kv[u].w * q2.w;
            float p3 = kv[u].x * q3.x + kv[u].y * q3.y + kv[u].z * q3.z + kv[u].w * q3.w;
#pragma unroll
            for (int off = 1; off <= 8; off <<= 1) {
                p0 += __shfl_xor_sync(0xffffffffu, p0, off);
                p1 += __shfl_xor_sync(0xffffffffu, p1, off);
                p2 += __shfl_xor_sync(0xffffffffu, p2, off);
                p3 += __shfl_xor_sync(0xffffffffu, p3, off);
            }
            if (dq == 0)
                *reinterpret_cast<float4*>(scT + row * 4) = make_float4(p0, p1, p2, p3);
        }
    }
    if (w < 2) {   // new K rows (4096..4099) from smem
        int r2 = w * 2 + sub;
        float4 kv = *reinterpret_cast<const float4*>(kn + r2 * HD_ + dq * 4);
        int row = S_ + r2;
        *reinterpret_cast<float4*>(okb + (size_t)row * HD_ + dq * 4) = kv;
        float p0 = kv.x * q0.x + kv.y * q0.y + kv.z * q0.z + kv.w * q0.w;
        float p1 = kv.x * q1.x + kv.y * q1.y + kv.z * q1.z + kv.w * q1.w;
        float p2 = kv.x * q2.x + kv.y * q2.y + kv.z * q2.z + kv.w * q2.w;
        float p3 = kv.x * q3.x + kv.y * q3.y + kv.z * q3.z + kv.w * q3.w;
#pragma unroll
        for (int off = 1; off <= 8; off <<= 1) {
            p0 += __shfl_xor_sync(0xffffffffu, p0, off);
            p1 += __shfl_xor_sync(0xffffffffu, p1, off);
            p2 += __shfl_xor_sync(0xffffffffu, p2, off);
            p3 += __shfl_xor_sync(0xffffffffu, p3, off);
        }
        if (dq == 0)
            *reinterpret_cast<float4*>(scT + row * 4) = make_float4(p0, p1, p2, p3);
    }
    __syncthreads();

    // ---- softmax over scT[s][qq]; thread t -> qq=t&3, s strided by 128 ----
    {
        int qq = t & 3, sidx = t >> 2;
        float mx = -1e30f;
        for (int s = sidx; s < SP_; s += 128) mx = fmaxf(mx, scT[s * 4 + qq]);
        red[t] = mx;
        __syncthreads();
        for (int wd = 256; wd >= 4; wd >>= 1) {
            if (t < wd) red[t] = fmaxf(red[t], red[t + wd]);
            __syncthreads();
        }
        float gm = red[qq];
        __syncthreads();
        float sum = 0.f;
        for (int s = sidx; s < SP_; s += 128) {
            float e = __expf(scT[s * 4 + qq] - gm);
            scT[s * 4 + qq] = e;
            sum += e;
        }
        red[t] = sum;
        __syncthreads();
        for (int wd = 256; wd >= 4; wd >>= 1) {
            if (t < wd) red[t] += red[t + wd];
            __syncthreads();
        }
        if (t < 4) inv4[t] = 1.f / red[t];
        __syncthreads();
    }

    // ---- pass 2: V stream once -> O accumulate + pres_v ----
    const float* vb  = pv + bh * S_ * HD_;
    float*       ovb = ov + bh * SP_ * HD_;
    float4 a0 = make_float4(0.f, 0.f, 0.f, 0.f);
    float4 a1 = a0, a2 = a0, a3 = a0;

    for (int base = w * 4; base < 2048; base += 64) {
        float4 vv[4];
#pragma unroll
        for (int u = 0; u < 4; u++) {
            int row = (base + u) * 2 + sub;
            vv[u] = *reinterpret_cast<const float4*>(vb + (size_t)row * HD_ + dq * 4);
        }
#pragma unroll
        for (int u = 0; u < 4; u++) {
            int row = (base + u) * 2 + sub;
            *reinterpret_cast<float4*>(ovb + (size_t)row * HD_ + dq * 4) = vv[u];
            float4 p = *reinterpret_cast<const float4*>(scT + row * 4);
            a0.x += p.x * vv[u].x; a0.y += p.x * vv[u].y; a0.z += p.x * vv[u].z; a0.w += p.x * vv[u].w;
            a1.x += p.y * vv[u].x; a1.y += p.y * vv[u].y; a1.z += p.y * vv[u].z; a1.w += p.y * vv[u].w;
            a2.x += p.z * vv[u].x; a2.y += p.z * vv[u].y; a2.z += p.z * vv[u].z; a2.w += p.z * vv[u].w;
            a3.x += p.w * vv[u].x; a3.y += p.w * vv[u].y; a3.z += p.w * vv[u].z; a3.w += p.w * vv[u].w;
        }
    }
    if (w < 2) {   // new V rows from smem
        int r2 = w * 2 + sub;
        float4 vv = *reinterpret_cast<const float4*>(vn + r2 * HD_ + dq * 4);
        int row = S_ + r2;
        *reinterpret_cast<float4*>(ovb + (size_t)row * HD_ + dq * 4) = vv;
        float4 p = *reinterpret_cast<const float4*>(scT + row * 4);
        a0.x += p.x * vv.x; a0.y += p.x * vv.y; a0.z += p.x * vv.z; a0.w += p.x * vv.w;
        a1.x += p.y * vv.x; a1.y += p.y * vv.y; a1.z += p.y * vv.z; a1.w += p.y * vv.w;
        a2.x += p.z * vv.x; a2.y += p.z * vv.y; a2.z += p.z * vv.z; a2.w += p.z * vv.w;
        a3.x += p.w * vv.x; a3.y += p.w * vv.y; a3.z += p.w * vv.z; a3.w += p.w * vv.w;
    }

    // combine the two row-halves (lane l <-> l+16), then stage per-warp partials
#pragma unroll
    for (int r = 0; r < 1; r++) {
        a0.x += __shfl_xor_sync(0xffffffffu, a0.x, 16); a0.y += __shfl_xor_sync(0xffffffffu, a0.y, 16);
        a0.z += __shfl_xor_sync(0xffffffffu, a0.z, 16); a0.w += __shfl_xor_sync(0xffffffffu, a0.w, 16);
        a1.x += __shfl_xor_sync(0xffffffffu, a1.x, 16); a1.y += __shfl_xor_sync(0xffffffffu, a1.y, 16);
        a1.z += __shfl_xor_sync(0xffffffffu, a1.z, 16); a1.w += __shfl_xor_sync(0xffffffffu, a1.w, 16);
        a2.x += __shfl_xor_sync(0xffffffffu, a2.x, 16); a2.y += __shfl_xor_sync(0xffffffffu, a2.y, 16);
        a2.z += __shfl_xor_sync(0xffffffffu, a2.z, 16); a2.w += __shfl_xor_sync(0xffffffffu, a2.w, 16);
        a3.x += __shfl_xor_sync(0xffffffffu, a3.x, 16); a3.y += __shfl_xor_sync(0xffffffffu, a3.y, 16);
        a3.z += __shfl_xor_sync(0xffffffffu, a3.z, 16); a3.w += __shfl_xor_sync(0xffffffffu, a3.w, 16);
    }
    if (sub == 0) {
        *reinterpret_cast<float4*>(opart + (w * 4 + 0) * 64 + dq * 4) = a0;
        *reinterpret_cast<float4*>(opart + (w * 4 + 1) * 64 + dq * 4) = a1;
        *reinterpret_cast<float4*>(opart + (w * 4 + 2) * 64 + dq * 4) = a2;
        *reinterpret_cast<float4*>(opart + (w * 4 + 3) * 64 + dq * 4) = a3;
    }
    __syncthreads();

    if (t < 256) {
        int qq = t >> 6, d = t & 63;
        float s = 0.f;
#pragma unroll
        for (int ww = 0; ww < 16; ww++)
            s += opart[(ww * 4 + qq) * 64 + d];
        o[(b * Q_ + qq) * D_ + h * HD_ + d] = s * inv4[qq];
    }
}

// ------------------------------- launcher -----------------------------------
extern "C" void kernel_launch(void* const* d_in, const int* in_sizes, int n_in,
                              void* d_out, int out_size) {
    const int*   ids    = (const int*)d_in[0];
    const int*   pos    = (const int*)d_in[1];
    const float* past_k = (const float*)d_in[2];
    const float* past_v = (const float*)d_in[3];
    const float* emb    = (const float*)d_in[4];
    const float* pemb   = (const float*)d_in[5];
    const float* qkv_w  = (const float*)d_in[6];
    const float* out_w  = (const float*)d_in[7];
    const float* fc1_w  = (const float*)d_in[8];
    const float* fc2_w  = (const float*)d_in[9];
    const float* lm_w   = (const float*)d_in[10];

    float* out    = (float*)d_out;
    float* logits = out;
    float* pres_k = out + (size_t)M32 * V_;
    float* pres_v = pres_k + (size_t)L_ * B_ * H_ * SP_ * HD_;

    float *x, *qkvb, *ob, *hb, *part;
    cudaGetSymbolAddress((void**)&x,    g_x);
    cudaGetSymbolAddress((void**)&qkvb, g_qkv);
    cudaGetSymbolAddress((void**)&ob,   g_o);
    cudaGetSymbolAddress((void**)&hb,   g_h);
    cudaGetSymbolAddress((void**)&part, g_part);

    const int GEMM_SMEM = 2 * 32 * BK_ * 4;               // 64 KB
    const int ATTN_SMEM = (5408 + SP_ * 4) * 4;           // 87232 B
    cudaFuncSetAttribute(gemm32_kernel, cudaFuncAttributeMaxDynamicSharedMemorySize, GEMM_SMEM);
    cudaFuncSetAttribute(attn_kernel,   cudaFuncAttributeMaxDynamicSharedMemorySize, ATTN_SMEM);

    embed_kernel<<<M32, 256>>>(ids, pos, emb, pemb);

    for (int l = 0; l < L_; l++) {
        // qkv = x @ qkv_w^T          N=3072 K=1024, 96 blocks
        gemm32_kernel<<<96, 256, GEMM_SMEM>>>(x, qkv_w + (size_t)l * 3 * D_ * D_,
                                              nullptr, qkvb, 3 * D_, D_, D_, 0);
        attn_kernel<<<B_ * H_, 512, ATTN_SMEM>>>(
            qkvb,
            past_k + (size_t)l * B_ * H_ * S_ * HD_,
            past_v + (size_t)l * B_ * H_ * S_ * HD_,
            pres_k + (size_t)l * B_ * H_ * SP_ * HD_,
            pres_v + (size_t)l * B_ * H_ * SP_ * HD_,
            ob);
        // x += o @ out_w^T           N=1024 K=1024, split-K 4 -> 128 blocks
        gemm32_kernel<<<32 * 4, 256, GEMM_SMEM>>>(ob, out_w + (size_t)l * D_ * D_,
                                                  nullptr, part, D_, D_, D_ / 4, 0);
        reduce_kernel<<<(32 * D_) / 256, 256>>>(part, x, x, D_, 4, 1);
        // h = relu(x @ fc1_w^T)      N=4096 K=1024, 128 blocks
        gemm32_kernel<<<128, 256, GEMM_SMEM>>>(x, fc1_w + (size_t)l * 4 * D_ * D_,
                                               nullptr, hb, 4 * D_, D_, D_, 2);
        // x += h @ fc2_w^T           N=1024 K=4096, split-K 4 -> 128 blocks
        gemm32_kernel<<<32 * 4, 256, GEMM_SMEM>>>(hb, fc2_w + (size_t)l * D_ * 4 * D_,
                                                  nullptr, part, D_, 4 * D_, D_, 0);
        reduce_kernel<<<(32 * D_) / 256, 256>>>(part, x, x, D_, 4, 1);
    }

    // logits = x @ lm_head^T         N=32000 K=1024, 1000 blocks
    gemm32_kernel<<<1000, 256, GEMM_SMEM>>>(x, lm_w, nullptr, logits, V_, D_, D_, 0);
}

// round 3
// speedup vs baseline: 3.3784x; 1.0025x over previous
#include <cuda_runtime.h>
#include <math.h>

#define L_  4
#define B_  8
#define H_  16
#define S_  4096
#define HD_ 64
#define D_  1024
#define Q_  4
#define V_  32000
#define SP_ (S_ + Q_)      // 4100
#define M32 (B_ * Q_)      // 32
#define SCALE_ 0.125f      // 1/sqrt(64)
#define BK_ 256

// ------------------------- scratch (no allocs allowed) ----------------------
__device__ float g_x[M32 * D_];
__device__ float g_qkv[M32 * 3 * D_];
__device__ float g_o[M32 * D_];
__device__ float g_h[M32 * 4 * D_];
__device__ float g_part[4 * M32 * 4096];   // split-K partials (KS<=4, N<=4096)

// ------------------------------ embedding -----------------------------------
__global__ void embed_kernel(const int* __restrict__ ids, const int* __restrict__ pos,
                             const float* __restrict__ emb, const float* __restrict__ pemb) {
    int m = blockIdx.x;
    int id = ids[m];
    int p  = pos[m];
    const float* e  = emb  + (size_t)id * D_;
    const float* pe = pemb + (size_t)p  * D_;
    for (int d = threadIdx.x; d < D_; d += blockDim.x)
        g_x[m * D_ + d] = e[d] + pe[d];
}

// ------------------------------ skinny GEMM ---------------------------------
// C[m,n] = dot(A[m,:], W[n,:]), M=32. BN=32 n per block, 8 warps x NT=4 n.
// Both W and A tiles are staged through smem with fully-coalesced global loads
// and register-prefetch double buffering. Compute: lane=m, a via swizzled
// float4 LDS (conflict-free), w via broadcast float4 LDS.
// kslen==K: write C with mode (0 store, 1 +res, 2 relu).
// kslen<K : grid.x = (N/32)*KS, write partials to Cout = g_part.
__global__ void __launch_bounds__(256, 2)
gemm32_kernel(const float* __restrict__ A, const float* __restrict__ W,
              const float* __restrict__ res, float* __restrict__ Cout,
              int N, int K, int kslen, int mode) {
    extern __shared__ float sm[];
    float4* w_sm4 = reinterpret_cast<float4*>(sm);            // [32][64] float4
    float4* a_sm4 = reinterpret_cast<float4*>(sm + 32 * BK_); // [64][32] float4 swizzled

    int t = threadIdx.x;
    int m = t & 31;
    int g = t >> 5;
    int nblocks = N >> 5;
    int nb = blockIdx.x % nblocks;
    int ks = blockIdx.x / nblocks;
    int k0 = ks * kslen;

    // loader mapping: 2048 float4 per tile, 8 per thread
    int lrow = t >> 6;          // 0..3, + 4*j
    int lcol = t & 63;          // float4 column within chunk

    const float* Wg = W + (size_t)(nb * 32 + lrow) * K + k0 + (size_t)lcol * 4;
    const float* Ag = A + (size_t)lrow * K + k0 + (size_t)lcol * 4;

    float4 wreg[8], areg[8];
#pragma unroll
    for (int j = 0; j < 8; j++) {
        wreg[j] = *reinterpret_cast<const float4*>(Wg + (size_t)(4 * j) * K);
        areg[j] = *reinterpret_cast<const float4*>(Ag + (size_t)(4 * j) * K);
    }

    float acc[4] = {0.f, 0.f, 0.f, 0.f};

    for (int kc = 0; kc < kslen; kc += BK_) {
        // commit prefetched tile to smem
#pragma unroll
        for (int j = 0; j < 8; j++) {
            int row = lrow + 4 * j;
            w_sm4[row * 64 + lcol] = wreg[j];
            a_sm4[lcol * 32 + (row ^ (lcol & 31))] = areg[j];
        }
        __syncthreads();

        if (kc + BK_ < kslen) {
#pragma unroll
            for (int j = 0; j < 8; j++) {
                wreg[j] = *reinterpret_cast<const float4*>(Wg + (size_t)(4 * j) * K + kc + BK_);
                areg[j] = *reinterpret_cast<const float4*>(Ag + (size_t)(4 * j) * K + kc + BK_);
            }
        }

        const float4* wrow = w_sm4 + g * 4 * 64;
#pragma unroll 4
        for (int kk4 = 0; kk4 < 64; kk4++) {
            float4 av = a_sm4[kk4 * 32 + (m ^ (kk4 & 31))];
            float4 w0 = wrow[kk4];
            float4 w1 = wrow[64 + kk4];
            float4 w2 = wrow[128 + kk4];
            float4 w3 = wrow[192 + kk4];
            acc[0] += av.x * w0.x + av.y * w0.y + av.z * w0.z + av.w * w0.w;
            acc[1] += av.x * w1.x + av.y * w1.y + av.z * w1.z + av.w * w1.w;
            acc[2] += av.x * w2.x + av.y * w2.y + av.z * w2.z + av.w * w2.w;
            acc[3] += av.x * w3.x + av.y * w3.y + av.z * w3.z + av.w * w3.w;
        }
        __syncthreads();
    }

    int n0 = nb * 32 + g * 4;
    if (kslen == K) {
#pragma unroll
        for (int j = 0; j < 4; j++) {
            int n = n0 + j;
            float v = acc[j];
            if (mode == 1)      v += res[(size_t)m * N + n];
            else if (mode == 2) v = fmaxf(v, 0.f);
            Cout[(size_t)m * N + n] = v;
        }
    } else {
#pragma unroll
        for (int j = 0; j < 4; j++)
            Cout[(size_t)(ks * 32 + m) * N + n0 + j] = acc[j];
    }
}

// split-K reduce: C = mode(sum_ks P, res)
__global__ void reduce_kernel(const float* __restrict__ P, const float* __restrict__ res,
                              float* __restrict__ C, int N, int KS, int mode) {
    int i = blockIdx.x * 256 + threadIdx.x;
    if (i >= 32 * N) return;
    float s = 0.f;
    for (int ks = 0; ks < KS; ks++) s += P[(size_t)ks * 32 * N + i];
    if (mode == 1)      s += res[i];
    else if (mode == 2) s = fmaxf(s, 0.f);
    C[i] = s;
}

// --------------------------- fused attention + KV copy ----------------------
// One block (512 thr) per (b,h). All global K/V traffic is coalesced:
// warp handles 2 rows per step; lane = (row-half sub, d-quarter dq).
// Pass 1: stream K -> scores (shfl-reduce over 16 lanes) + pres_k copy.
// Pass 2: stream V once, accumulate all 4 queries per lane + pres_v copy.
__global__ void __launch_bounds__(512, 1)
attn_kernel(const float* __restrict__ qkv,
            const float* __restrict__ pk, const float* __restrict__ pv,
            float* __restrict__ ok, float* __restrict__ ov,
            float* __restrict__ o) {
    extern __shared__ float sm[];
    float* q_sm  = sm;            // [4][64] pre-scaled
    float* kn    = sm + 256;      // new K rows [4][64]
    float* vn    = sm + 512;      // new V rows [4][64]
    float* red   = sm + 768;      // [512]
    float* inv4  = sm + 1280;     // [4] (padded)
    float* opart = sm + 1312;     // [16 warps][4 qq][64 d]
    float* scT   = sm + 5408;     // [SP][4] interleaved scores

    int t = threadIdx.x;
    int b = blockIdx.x >> 4;
    int h = blockIdx.x & 15;

    if (t < 256) {
        int qq = t >> 6, d = t & 63;
        int rowi = (b * Q_ + qq) * 3 * D_ + h * HD_ + d;
        q_sm[t] = qkv[rowi] * SCALE_;
        kn[t]   = qkv[rowi + D_];
        vn[t]   = qkv[rowi + 2 * D_];
    }
    __syncthreads();

    int w   = t >> 5;
    int l   = t & 31;
    int sub = l >> 4;         // 0/1: which of the 2 rows
    int dq  = l & 15;         // d-quarter (4 floats)

    size_t bh = (size_t)(b * H_ + h);
    const float* kb  = pk + bh * S_ * HD_;
    float*       okb = ok + bh * SP_ * HD_;

    float4 q0 = *reinterpret_cast<const float4*>(q_sm +       dq * 4);
    float4 q1 = *reinterpret_cast<const float4*>(q_sm +  64 + dq * 4);
    float4 q2 = *reinterpret_cast<const float4*>(q_sm + 128 + dq * 4);
    float4 q3 = *reinterpret_cast<const float4*>(q_sm + 192 + dq * 4);

    // ---- pass 1: K stream -> scores + pres_k ----
    for (int base = w * 4; base < 2048; base += 64) {
        float4 kv[4];
#pragma unroll
        for (int u = 0; u < 4; u++) {
            int row = (base + u) * 2 + sub;
            kv[u] = *reinterpret_cast<const float4*>(kb + (size_t)row * HD_ + dq * 4);
        }
#pragma unroll
        for (int u = 0; u < 4; u++) {
            int row = (base + u) * 2 + sub;
            *reinterpret_cast<float4*>(okb + (size_t)row * HD_ + dq * 4) = kv[u];
            float p0 = kv[u].x * q0.x + kv[u].y * q0.y + kv[u].z * q0.z + kv[u].w * q0.w;
            float p1 = kv[u].x * q1.x + kv[u].y * q1.y + kv[u].z * q1.z + kv[u].w * q1.w;
            float p2 = kv[u].x * q2.x + kv[u].y * q2.y + kv[u].z * q2.z + kv[u].w * q2.w;
            float p3 = kv[u].x * q3.x + kv[u].y * q3.y + kv[u].z * q3.z + kv[u].w * q3.w;
#pragma unroll
            for (int off = 1; off <= 8; off <<= 1) {
                p0 += __shfl_xor_sync(0xffffffffu, p0, off);
                p1 += __shfl_xor_sync(0xffffffffu, p1, off);
                p2 += __shfl_xor_sync(0xffffffffu, p2, off);
                p3 += __shfl_xor_sync(0xffffffffu, p3, off);
            }
            if (dq == 0)
                *reinterpret_cast<float4*>(scT + row * 4) = make_float4(p0, p1, p2, p3);
        }
    }
    if (w < 2) {   // new K rows (4096..4099) from smem
        int r2 = w * 2 + sub;
        float4 kv = *reinterpret_cast<const float4*>(kn + r2 * HD_ + dq * 4);
        int row = S_ + r2;
        *reinterpret_cast<float4*>(okb + (size_t)row * HD_ + dq * 4) = kv;
        float p0 = kv.x * q0.x + kv.y * q0.y + kv.z * q0.z + kv.w * q0.w;
        float p1 = kv.x * q1.x + kv.y * q1.y + kv.z * q1.z + kv.w * q1.w;
        float p2 = kv.x * q2.x + kv.y * q2.y + kv.z * q2.z + kv.w * q2.w;
        float p3 = kv.x * q3.x + kv.y * q3.y + kv.z * q3.z + kv.w * q3.w;
#pragma unroll
        for (int off = 1; off <= 8; off <<= 1) {
            p0 += __shfl_xor_sync(0xffffffffu, p0, off);
            p1 += __shfl_xor_sync(0xffffffffu, p1, off);
            p2 += __shfl_xor_sync(0xffffffffu, p2, off);
            p3 += __shfl_xor_sync(0xffffffffu, p3, off);
        }
        if (dq == 0)
            *reinterpret_cast<float4*>(scT + row * 4) = make_float4(p0, p1, p2, p3);
    }
    __syncthreads();

    // ---- softmax over scT[s][qq]; thread t -> qq=t&3, s strided by 128 ----
    {
        int qq = t & 3, sidx = t >> 2;
        float mx = -1e30f;
        for (int s = sidx; s < SP_; s += 128) mx = fmaxf(mx, scT[s * 4 + qq]);
        red[t] = mx;
        __syncthreads();
        for (int wd = 256; wd >= 4; wd >>= 1) {
            if (t < wd) red[t] = fmaxf(red[t], red[t + wd]);
            __syncthreads();
        }
        float gm = red[qq];
        __syncthreads();
        float sum = 0.f;
        for (int s = sidx; s < SP_; s += 128) {
            float e = __expf(scT[s * 4 + qq] - gm);
            scT[s * 4 + qq] = e;
            sum += e;
        }
        red[t] = sum;
        __syncthreads();
        for (int wd = 256; wd >= 4; wd >>= 1) {
            if (t < wd) red[t] += red[t + wd];
            __syncthreads();
        }
        if (t < 4) inv4[t] = 1.f / red[t];
        __syncthreads();
    }

    // ---- pass 2: V stream once -> O accumulate + pres_v ----
    const float* vb  = pv + bh * S_ * HD_;
    float*       ovb = ov + bh * SP_ * HD_;
    float4 a0 = make_float4(0.f, 0.f, 0.f, 0.f);
    float4 a1 = a0, a2 = a0, a3 = a0;

    for (int base = w * 4; base < 2048; base += 64) {
        float4 vv[4];
#pragma unroll
        for (int u = 0; u < 4; u++) {
            int row = (base + u) * 2 + sub;
            vv[u] = *reinterpret_cast<const float4*>(vb + (size_t)row * HD_ + dq * 4);
        }
#pragma unroll
        for (int u = 0; u < 4; u++) {
            int row = (base + u) * 2 + sub;
            *reinterpret_cast<float4*>(ovb + (size_t)row * HD_ + dq * 4) = vv[u];
            float4 p = *reinterpret_cast<const float4*>(scT + row * 4);
            a0.x += p.x * vv[u].x; a0.y += p.x * vv[u].y; a0.z += p.x * vv[u].z; a0.w += p.x * vv[u].w;
            a1.x += p.y * vv[u].x; a1.y += p.y * vv[u].y; a1.z += p.y * vv[u].z; a1.w += p.y * vv[u].w;
            a2.x += p.z * vv[u].x; a2.y += p.z * vv[u].y; a2.z += p.z * vv[u].z; a2.w += p.z * vv[u].w;
            a3.x += p.w * vv[u].x; a3.y += p.w * vv[u].y; a3.z += p.w * vv[u].z; a3.w += p.w * vv[u].w;
        }
    }
    if (w < 2) {   // new V rows from smem
        int r2 = w * 2 + sub;
        float4 vv = *reinterpret_cast<const float4*>(vn + r2 * HD_ + dq * 4);
        int row = S_ + r2;
        *reinterpret_cast<float4*>(ovb + (size_t)row * HD_ + dq * 4) = vv;
        float4 p = *reinterpret_cast<const float4*>(scT + row * 4);
        a0.x += p.x * vv.x; a0.y += p.x * vv.y; a0.z += p.x * vv.z; a0.w += p.x * vv.w;
        a1.x += p.y * vv.x; a1.y += p.y * vv.y; a1.z += p.y * vv.z; a1.w += p.y * vv.w;
        a2.x += p.z * vv.x; a2.y += p.z * vv.y; a2.z += p.z * vv.z; a2.w += p.z * vv.w;
        a3.x += p.w * vv.x; a3.y += p.w * vv.y; a3.z += p.w * vv.z; a3.w += p.w * vv.w;
    }

    // combine the two row-halves (lane l <-> l+16), then stage per-warp partials
#pragma unroll
    for (int r = 0; r < 1; r++) {
        a0.x += __shfl_xor_sync(0xffffffffu, a0.x, 16); a0.y += __shfl_xor_sync(0xffffffffu, a0.y, 16);
        a0.z += __shfl_xor_sync(0xffffffffu, a0.z, 16); a0.w += __shfl_xor_sync(0xffffffffu, a0.w, 16);
        a1.x += __shfl_xor_sync(0xffffffffu, a1.x, 16); a1.y += __shfl_xor_sync(0xffffffffu, a1.y, 16);
        a1.z += __shfl_xor_sync(0xffffffffu, a1.z, 16); a1.w += __shfl_xor_sync(0xffffffffu, a1.w, 16);
        a2.x += __shfl_xor_sync(0xffffffffu, a2.x, 16); a2.y += __shfl_xor_sync(0xffffffffu, a2.y, 16);
        a2.z += __shfl_xor_sync(0xffffffffu, a2.z, 16); a2.w += __shfl_xor_sync(0xffffffffu, a2.w, 16);
        a3.x += __shfl_xor_sync(0xffffffffu, a3.x, 16); a3.y += __shfl_xor_sync(0xffffffffu, a3.y, 16);
        a3.z += __shfl_xor_sync(0xffffffffu, a3.z, 16); a3.w += __shfl_xor_sync(0xffffffffu, a3.w, 16);
    }
    if (sub == 0) {
        *reinterpret_cast<float4*>(opart + (w * 4 + 0) * 64 + dq * 4) = a0;
        *reinterpret_cast<float4*>(opart + (w * 4 + 1) * 64 + dq * 4) = a1;
        *reinterpret_cast<float4*>(opart + (w * 4 + 2) * 64 + dq * 4) = a2;
        *reinterpret_cast<float4*>(opart + (w * 4 + 3) * 64 + dq * 4) = a3;
    }
    __syncthreads();

    if (t < 256) {
        int qq = t >> 6, d = t & 63;
        float s = 0.f;
#pragma unroll
        for (int ww = 0; ww < 16; ww++)
            s += opart[(ww * 4 + qq) * 64 + d];
        o[(b * Q_ + qq) * D_ + h * HD_ + d] = s * inv4[qq];
    }
}

// ------------------------------- launcher -----------------------------------
extern "C" void kernel_launch(void* const* d_in, const int* in_sizes, int n_in,
                              void* d_out, int out_size) {
    const int*   ids    = (const int*)d_in[0];
    const int*   pos    = (const int*)d_in[1];
    const float* past_k = (const float*)d_in[2];
    const float* past_v = (const float*)d_in[3];
    const float* emb    = (const float*)d_in[4];
    const float* pemb   = (const float*)d_in[5];
    const float* qkv_w  = (const float*)d_in[6];
    const float* out_w  = (const float*)d_in[7];
    const float* fc1_w  = (const float*)d_in[8];
    const float* fc2_w  = (const float*)d_in[9];
    const float* lm_w   = (const float*)d_in[10];

    float* out    = (float*)d_out;
    float* logits = out;
    float* pres_k = out + (size_t)M32 * V_;
    float* pres_v = pres_k + (size_t)L_ * B_ * H_ * SP_ * HD_;

    float *x, *qkvb, *ob, *hb, *part;
    cudaGetSymbolAddress((void**)&x,    g_x);
    cudaGetSymbolAddress((void**)&qkvb, g_qkv);
    cudaGetSymbolAddress((void**)&ob,   g_o);
    cudaGetSymbolAddress((void**)&hb,   g_h);
    cudaGetSymbolAddress((void**)&part, g_part);

    const int GEMM_SMEM = 2 * 32 * BK_ * 4;               // 64 KB
    const int ATTN_SMEM = (5408 + SP_ * 4) * 4;           // 87232 B
    cudaFuncSetAttribute(gemm32_kernel, cudaFuncAttributeMaxDynamicSharedMemorySize, GEMM_SMEM);
    cudaFuncSetAttribute(attn_kernel,   cudaFuncAttributeMaxDynamicSharedMemorySize, ATTN_SMEM);

    embed_kernel<<<M32, 256>>>(ids, pos, emb, pemb);

    for (int l = 0; l < L_; l++) {
        // qkv = x @ qkv_w^T          N=3072 K=1024, 96 blocks
        gemm32_kernel<<<96, 256, GEMM_SMEM>>>(x, qkv_w + (size_t)l * 3 * D_ * D_,
                                              nullptr, qkvb, 3 * D_, D_, D_, 0);
        attn_kernel<<<B_ * H_, 512, ATTN_SMEM>>>(
            qkvb,
            past_k + (size_t)l * B_ * H_ * S_ * HD_,
            past_v + (size_t)l * B_ * H_ * S_ * HD_,
            pres_k + (size_t)l * B_ * H_ * SP_ * HD_,
            pres_v + (size_t)l * B_ * H_ * SP_ * HD_,
            ob);
        // x += o @ out_w^T           N=1024 K=1024, split-K 4 -> 128 blocks
        gemm32_kernel<<<32 * 4, 256, GEMM_SMEM>>>(ob, out_w + (size_t)l * D_ * D_,
                                                  nullptr, part, D_, D_, D_ / 4, 0);
        reduce_kernel<<<(32 * D_) / 256, 256>>>(part, x, x, D_, 4, 1);
        // h = relu(x @ fc1_w^T)      N=4096 K=1024, 128 blocks
        gemm32_kernel<<<128, 256, GEMM_SMEM>>>(x, fc1_w + (size_t)l * 4 * D_ * D_,
                                               nullptr, hb, 4 * D_, D_, D_, 2);
        // x += h @ fc2_w^T           N=1024 K=4096, split-K 4 -> 128 blocks
        gemm32_kernel<<<32 * 4, 256, GEMM_SMEM>>>(hb, fc2_w + (size_t)l * D_ * 4 * D_,
                                                  nullptr, part, D_, 4 * D_, D_, 0);
        reduce_kernel<<<(32 * D_) / 256, 256>>>(part, x, x, D_, 4, 1);
    }

    // logits = x @ lm_head^T         N=32000 K=1024, 1000 blocks
    gemm32_kernel<<<1000, 256, GEMM_SMEM>>>(x, lm_w, nullptr, logits, V_, D_, D_, 0);
}